// round 10
// baseline (speedup 1.0000x reference)
#include <cuda_runtime.h>
#include <cstdint>

// NMS_20933670600803  — heatmap (B,1,14,14) f32 -> [m1 | m2] f32
//
// One warp per item, float4 I/O. Keys (validated R4-R9, rel_err 0):
//   key = (max(fb, bits(0.6f)) << 8) + (0xE66666FF - i)  [mod 2^32]
// below-threshold / suppressed -> key = 255 - i; unsigned max == jnp.argmax
// (max value, tie -> smallest index). Warp reduce = one REDUX.MAX.U32.
// Dead slots (i >= 196) load 0.0 -> key = 255-i <= 59 < 60 <= live keys.
//
// R10: suppression table stores the final AND operand per element
// (0x000000FF if inside the window -> key collapses to 255-i; 0xFFFFFFFF
// otherwise) -> ONE LOP per element, no PRMT. 200KB global table, read as
// two coalesced 512B LDG.128 per iteration, L1/L2-resident (heatmap/output
// use streaming hints). Emission on the fma pipe: IMAD.HI row decode,
// IMAD pv, r2 = 1.0f - r1 (FADD, exact on {0,1}).

#define NPIX 196
#define NVEC 49
#define WPB  8
#define THREADS (WPB * 32)
#define KTHR   0x3F19999Au      // __float_as_uint(0.6f)
#define MUL14  306790400u       // 18725 << 14 ; eu = umulhi(i, MUL14) = i/14 (i<256)

struct alignas(16) AndTable {
    // w[bi][0][lane] : uint4 AND-operands for elements 4*lane .. 4*lane+3
    // w[bi][1][lane] : uint4 AND-operands for elements 128+4*lane .. +3
    unsigned w[196][2][32][4];
    constexpr AndTable() : w{} {
        for (int bi = 0; bi < 196; ++bi) {
            const int x = bi / 14, y = bi % 14;
            const int x1 = (x - 5 > 0) ? x - 5 : 0;
            const int x2 = (x + 5 < 15) ? x + 5 : 15;
            const int y1 = (y - 5 > 0) ? y - 5 : 0;
            const int y2 = (y + 5 < 15) ? y + 5 : 15;
            for (int half = 0; half < 2; ++half)
                for (int lane = 0; lane < 32; ++lane)
                    for (int c = 0; c < 4; ++c) {
                        const int i = half * 128 + 4 * lane + c;
                        unsigned op = 0xFFFFFFFFu;            // not suppressed / dead
                        if (i < 196) {
                            const int eu = i / 14, ev = i % 14;
                            if (eu >= x1 && eu < x2 && ev >= y1 && ev < y2)
                                op = 0x000000FFu;             // suppress: keep index byte
                        }
                        w[bi][half][lane][c] = op;
                    }
        }
    }
};
__device__ const AndTable g_tbl;     // ~200KB global, constexpr-initialized

__global__ __launch_bounds__(THREADS)
void nms_masks_kernel(const float4* __restrict__ hm,
                      float4* __restrict__ out,
                      int B)
{
    const int warp = blockIdx.x * WPB + (threadIdx.x >> 5);
    const int lane = threadIdx.x & 31;
    if (warp >= B) return;

    const float4* __restrict__ p = hm + (size_t)warp * NVEC;
    const float4 va = __ldcs(p + lane);            // elements 4j..4j+3
    const bool has2 = (lane < 17);
    float4 vb = make_float4(0.f, 0.f, 0.f, 0.f);
    if (has2) vb = __ldcs(p + lane + 32);          // elements 128+4j..

    const int i0 = 4 * lane;
    const int i1 = 128 + 4 * lane;

    unsigned key[8];
    {
        const float vals[8] = {va.x, va.y, va.z, va.w, vb.x, vb.y, vb.z, vb.w};
#pragma unroll
        for (int c = 0; c < 8; ++c) {
            const int i = (c < 4) ? (i0 + c) : (i1 + c - 4);
            const unsigned fb = __float_as_uint(vals[c]);
            const unsigned M  = (fb > KTHR) ? fb : KTHR;          // IMNMX.U32
            key[c] = M * 256u + (0xE66666FFu - (unsigned)i);      // IMAD (fma pipe)
        }
    }

    int bis[4];
#pragma unroll
    for (int it = 0; it < 4; ++it) {
        unsigned m = max(max(max(key[0], key[1]), max(key[2], key[3])),
                         max(max(key[4], key[5]), max(key[6], key[7])));
        const unsigned w = __reduce_max_sync(0xffffffffu, m);     // REDUX.MAX.U32
        const int bi = (int)((~w) & 0xFFu);                       // 255 - (w & 0xFF)
        bis[it] = bi;

        if (it < 3) {
            // two coalesced LDG.128 (512B per warp each), L1-resident table
            const uint4 t0 = __ldg(reinterpret_cast<const uint4*>(g_tbl.w[bi][0][lane]));
            const uint4 t1 = __ldg(reinterpret_cast<const uint4*>(g_tbl.w[bi][1][lane]));
            key[0] &= t0.x;  key[1] &= t0.y;  key[2] &= t0.z;  key[3] &= t0.w;
            key[4] &= t1.x;  key[5] &= t1.y;  key[6] &= t1.z;  key[7] &= t1.w;
        }
    }

    // decode peaks after the loop (off the REDUX->LDG critical path)
    int px[4], py[4], pk[4];
#pragma unroll
    for (int t = 0; t < 4; ++t) {
        const int x = (int)__umulhi((unsigned)bis[t], MUL14);     // bi / 14
        const int y = bis[t] - 14 * x;
        px[t] = x; py[t] = y; pk[t] = x | (y << 4);
    }

    // farthest pair among 4 peaks (6 pairs, first-tie argmax), packed key
    unsigned kbest = 0;
    {
        const int pa[6] = {0, 0, 0, 1, 1, 2};
        const int pb[6] = {1, 2, 3, 2, 3, 3};
#pragma unroll
        for (int q = 0; q < 6; ++q) {
            const int dx = px[pb[q]] - px[pa[q]];
            const int dy = py[pb[q]] - py[pa[q]];
            const int d  = dx * dx + dy * dy;      // <= 338
            const unsigned kd = ((unsigned)d << 20) | ((unsigned)(5 - q) << 16)
                              | (unsigned)(pk[pa[q]] | (pk[pb[q]] << 8));
            kbest = (kbest > kd) ? kbest : kd;
        }
    }
    const int ax = (int)(kbest & 0xFu);
    const int ay = (int)((kbest >> 4)  & 0xFu);
    const int bx = (int)((kbest >> 8)  & 0xFu);
    const int by = (int)((kbest >> 12) & 0xFu);

    // d1 - d2 = Cy*i + Cg*eu + mCc   (ev = i - 14*eu folded in)
    const int dxc = bx - ax, dyc = by - ay;
    const int Cy  = 2 * dyc;
    const int Cg  = 2 * dxc - 14 * Cy;
    const int mCc = -(dxc * (ax + bx) + dyc * (ay + by));

    float4* __restrict__ o1 = out + (size_t)warp * NVEC;
    float4* __restrict__ o2 = o1 + (size_t)B * NVEC;

    {
        float r1[4], r2[4];
#pragma unroll
        for (int c = 0; c < 4; ++c) {
            const int i  = i0 + c;
            const int eu = (int)__umulhi((unsigned)i, MUL14);        // IMAD.HI (fma)
            const int pv = Cy * i + (Cg * eu + mCc);                 // 2x IMAD (fma)
            const unsigned m1b = ((unsigned)pv >> 31) * 0x3F800000u; // SHF + IMAD
            r1[c] = __uint_as_float(m1b);      // 1.0f if d1<d2 else 0.0f
            r2[c] = 1.0f - r1[c];              // FADD (fma pipe), exact on {0,1}
        }
        __stcs(o1 + lane, make_float4(r1[0], r1[1], r1[2], r1[3]));
        __stcs(o2 + lane, make_float4(r2[0], r2[1], r2[2], r2[3]));
    }
    if (has2) {
        float r1[4], r2[4];
#pragma unroll
        for (int c = 0; c < 4; ++c) {
            const int i  = i1 + c;
            const int eu = (int)__umulhi((unsigned)i, MUL14);
            const int pv = Cy * i + (Cg * eu + mCc);
            const unsigned m1b = ((unsigned)pv >> 31) * 0x3F800000u;
            r1[c] = __uint_as_float(m1b);
            r2[c] = 1.0f - r1[c];
        }
        __stcs(o1 + lane + 32, make_float4(r1[0], r1[1], r1[2], r1[3]));
        __stcs(o2 + lane + 32, make_float4(r2[0], r2[1], r2[2], r2[3]));
    }
}

extern "C" void kernel_launch(void* const* d_in, const int* in_sizes, int n_in,
                              void* d_out, int out_size)
{
    const float4* hm  = (const float4*)d_in[0];
    float4*       out = (float4*)d_out;
    const int B = in_sizes[0] / NPIX;              // 131072
    const int grid = (B + WPB - 1) / WPB;
    nms_masks_kernel<<<grid, THREADS>>>(hm, out, B);
}